// round 1
// baseline (speedup 1.0000x reference)
#include <cuda_runtime.h>

// Problem constants (fixed by the dataset)
#define T_TOK 2048
#define KDIM  2048
#define IDIM  1024
#define NEXP  8
#define NJOBS 9          // 8 routed experts + 1 shared expert (job 8)
#define CAP   4096       // worst case: every token routes both slots to one expert
#define TOPK  2

// ---------------------------------------------------------------------------
// Scratch (device globals: no allocation allowed)
// ---------------------------------------------------------------------------
__device__ int   g_cnt[NJOBS];
__device__ int   g_tok[NJOBS * CAP];
__device__ float g_prob[NJOBS * CAP];
__device__ __align__(16) float g_act[(size_t)NJOBS * CAP * IDIM];   // ~151 MB

// ---------------------------------------------------------------------------
// FP4 E2M1 dequant helper:
// nibble = s|e2|e1|m. magnitudes {0,.5,1,1.5,2,3,4,6} -> 2x = {0,1,2,3,4,6,8,12}
// packed LUT nibbles (idx 0..7): 0,1,2,3,4,6,8,C  => 0xC8643210
// value = sign * (lut>>4e &0xF) * 0.5 * scale ; fold 0.5 into scale.
// ---------------------------------------------------------------------------
__device__ __forceinline__ float fp4_dequant(unsigned nib, float half_scale) {
    unsigned mag = (0xC8643210u >> ((nib & 7u) * 4)) & 0xFu;
    float f = (float)mag;
    f = __int_as_float(__float_as_int(f) | ((nib & 8u) << 28));  // sign bit
    return f * half_scale;
}

// ---------------------------------------------------------------------------
// Kernel 0: zero output + per-expert counters
// ---------------------------------------------------------------------------
__global__ void k_zero(float* __restrict__ out) {
    int i = blockIdx.x * 256 + threadIdx.x;
    out[i] = 0.0f;
    if (blockIdx.x == 0 && threadIdx.x < NJOBS) g_cnt[threadIdx.x] = 0;
}

// ---------------------------------------------------------------------------
// Kernel 1: build per-expert token lists (job 8 = shared expert, all tokens)
// ---------------------------------------------------------------------------
__global__ void k_route(const int* __restrict__ ids, const float* __restrict__ probs) {
    int t = blockIdx.x * 256 + threadIdx.x;
    #pragma unroll
    for (int s = 0; s < TOPK; s++) {
        int e   = ids[t * TOPK + s];
        float p = probs[t * TOPK + s];
        int pos = atomicAdd(&g_cnt[e], 1);
        g_tok[e * CAP + pos]  = t;
        g_prob[e * CAP + pos] = p;
    }
    g_tok[NEXP * CAP + t]  = t;      // shared expert: identity list
    g_prob[NEXP * CAP + t] = 1.0f;   // SHARED_EXPERT_WEIGHT = 1.0
    if (t == 0) g_cnt[NEXP] = T_TOK;
}

// ---------------------------------------------------------------------------
// Kernel 2: grouped gate_up GEMM + silu epilogue
//   A = x rows gathered per expert  [tokens x K]
//   W = fp4 packed [K/8, 2I] + scales [K/64, 2I]
//   act[job][pos][i] = silu(gate)*up
// Tile: 64 tokens x 64 i-cols (gate col n, up col I+n), K-chunk 64.
// Dynamic smem: xs 64x64 | ws 64x128 | ts 64
// ---------------------------------------------------------------------------
__global__ __launch_bounds__(256) void k_gemm1(
    const float* __restrict__ x,
    const int* __restrict__ wq,  const float* __restrict__ sc,    // routed
    const int* __restrict__ wqs, const float* __restrict__ scs)   // shared
{
    extern __shared__ float dyn[];
    float* xs = dyn;                  // [64][64]
    float* ws = dyn + 64 * 64;        // [64][128] : cols 0-63 gate, 64-127 up
    int*   ts = (int*)(dyn + 64 * 64 + 64 * 128);

    const int job  = blockIdx.z;
    const int cnt  = g_cnt[job];
    const int base = blockIdx.x * 64;
    if (base >= cnt) return;

    const int* W; const float* S;
    if (job < NEXP) {
        W = wq + (size_t)job * (KDIM / 8) * (2 * IDIM);
        S = sc + (size_t)job * (KDIM / 64) * (2 * IDIM);
    } else { W = wqs; S = scs; }

    const int n0  = blockIdx.y * 64;
    const int tid = threadIdx.x;
    const int tx = tid & 15, ty = tid >> 4;

    if (tid < 64) {
        int pos = base + tid;
        ts[tid] = (pos < cnt) ? g_tok[job * CAP + pos] : -1;
    }
    __syncthreads();

    float ag[4][4] = {}, au[4][4] = {};

    const int fkg = tid & 15;             // fill: kk-group (x4 floats)
    const int dc  = tid & 127;            // dequant col 0..127
    const int dr0 = tid >> 7;             // dequant row phase 0..1
    const int cw  = (dc < 64) ? (n0 + dc) : (IDIM + n0 + (dc - 64));

    for (int kc = 0; kc < KDIM; kc += 64) {
        // ---- fill xs (64 tokens x 64 k) ----
        #pragma unroll
        for (int it = 0; it < 4; it++) {
            int tok = (tid >> 4) + it * 16;
            int t_  = ts[tok];
            float4 v = make_float4(0.f, 0.f, 0.f, 0.f);
            if (t_ >= 0) v = *(const float4*)(x + (size_t)t_ * KDIM + kc + fkg * 4);
            *(float4*)&xs[tok * 64 + fkg * 4] = v;
        }
        // ---- dequant ws (64 k x 128 cols) ----
        float scv = S[(size_t)(kc >> 6) * (2 * IDIM) + cw] * 0.5f;
        #pragma unroll
        for (int rr = 0; rr < 4; rr++) {
            int r = dr0 + rr * 2;
            unsigned word = (unsigned)W[(size_t)(kc / 8 + r) * (2 * IDIM) + cw];
            #pragma unroll
            for (int j = 0; j < 8; j++)
                ws[(r * 8 + j) * 128 + dc] = fp4_dequant((word >> (4 * j)) & 0xFu, scv);
        }
        __syncthreads();
        // ---- inner product ----
        #pragma unroll 4
        for (int kk = 0; kk < 64; kk++) {
            float a[4];
            #pragma unroll
            for (int i = 0; i < 4; i++) a[i] = xs[(ty * 4 + i) * 64 + kk];
            const float4 wg = *(const float4*)&ws[kk * 128 + tx * 4];
            const float4 wu = *(const float4*)&ws[kk * 128 + 64 + tx * 4];
            #pragma unroll
            for (int i = 0; i < 4; i++) {
                ag[i][0] += a[i] * wg.x; ag[i][1] += a[i] * wg.y;
                ag[i][2] += a[i] * wg.z; ag[i][3] += a[i] * wg.w;
                au[i][0] += a[i] * wu.x; au[i][1] += a[i] * wu.y;
                au[i][2] += a[i] * wu.z; au[i][3] += a[i] * wu.w;
            }
        }
        __syncthreads();
    }

    // ---- epilogue: silu(gate) * up -> g_act ----
    #pragma unroll
    for (int i = 0; i < 4; i++) {
        int pos = base + ty * 4 + i;
        if (pos < cnt) {
            float4 o;
            float g;
            g = ag[i][0]; o.x = (g / (1.0f + __expf(-g))) * au[i][0];
            g = ag[i][1]; o.y = (g / (1.0f + __expf(-g))) * au[i][1];
            g = ag[i][2]; o.z = (g / (1.0f + __expf(-g))) * au[i][2];
            g = ag[i][3]; o.w = (g / (1.0f + __expf(-g))) * au[i][3];
            *(float4*)&g_act[(size_t)job * CAP * IDIM + (size_t)pos * IDIM + n0 + tx * 4] = o;
        }
    }
}

// ---------------------------------------------------------------------------
// Kernel 3: grouped down GEMM, prob-weighted atomic accumulate into out
//   A = act [tokens x I], W = fp4 packed [I/8, K] + scales [I/64, K]
// Tile: 64 tokens x 64 k-cols, I-chunk 64.
// ---------------------------------------------------------------------------
__global__ __launch_bounds__(256) void k_gemm2(
    float* __restrict__ out,
    const int* __restrict__ wq,  const float* __restrict__ sc,
    const int* __restrict__ wqs, const float* __restrict__ scs)
{
    __shared__ float xs[64 * 64];
    __shared__ float ws[64 * 64];
    __shared__ int   ts[64];
    __shared__ float psm[64];

    const int job  = blockIdx.z;
    const int cnt  = g_cnt[job];
    const int base = blockIdx.x * 64;
    if (base >= cnt) return;

    const int* W; const float* S;
    if (job < NEXP) {
        W = wq + (size_t)job * (IDIM / 8) * KDIM;
        S = sc + (size_t)job * (IDIM / 64) * KDIM;
    } else { W = wqs; S = scs; }

    const int n0  = blockIdx.y * 64;
    const int tid = threadIdx.x;
    const int tx = tid & 15, ty = tid >> 4;

    if (tid < 64) {
        int pos = base + tid;
        ts[tid]  = (pos < cnt) ? g_tok[job * CAP + pos] : -1;
        psm[tid] = (pos < cnt) ? g_prob[job * CAP + pos] : 0.0f;
    }
    __syncthreads();

    float acc[4][4] = {};

    const int fkg = tid & 15;
    const int dc  = tid & 63;
    const int dr0 = tid >> 6;          // 0..3
    const int cw  = n0 + dc;

    for (int kc = 0; kc < IDIM; kc += 64) {
        // ---- fill xs from g_act ----
        #pragma unroll
        for (int it = 0; it < 4; it++) {
            int tok = (tid >> 4) + it * 16;
            int pos = base + tok;
            float4 v = make_float4(0.f, 0.f, 0.f, 0.f);
            if (pos < cnt)
                v = *(const float4*)&g_act[(size_t)job * CAP * IDIM + (size_t)pos * IDIM + kc + fkg * 4];
            *(float4*)&xs[tok * 64 + fkg * 4] = v;
        }
        // ---- dequant ws (64 i x 64 cols) ----
        float scv = S[(size_t)(kc >> 6) * KDIM + cw] * 0.5f;
        #pragma unroll
        for (int rr = 0; rr < 2; rr++) {
            int r = dr0 + rr * 4;
            unsigned word = (unsigned)W[(size_t)(kc / 8 + r) * KDIM + cw];
            #pragma unroll
            for (int j = 0; j < 8; j++)
                ws[(r * 8 + j) * 64 + dc] = fp4_dequant((word >> (4 * j)) & 0xFu, scv);
        }
        __syncthreads();
        // ---- inner product ----
        #pragma unroll 4
        for (int kk = 0; kk < 64; kk++) {
            float a[4];
            #pragma unroll
            for (int i = 0; i < 4; i++) a[i] = xs[(ty * 4 + i) * 64 + kk];
            const float4 w = *(const float4*)&ws[kk * 64 + tx * 4];
            #pragma unroll
            for (int i = 0; i < 4; i++) {
                acc[i][0] += a[i] * w.x; acc[i][1] += a[i] * w.y;
                acc[i][2] += a[i] * w.z; acc[i][3] += a[i] * w.w;
            }
        }
        __syncthreads();
    }

    // ---- epilogue: out[t][k] += prob * acc ----
    #pragma unroll
    for (int i = 0; i < 4; i++) {
        int pos = base + ty * 4 + i;
        if (pos < cnt) {
            int   t = ts[ty * 4 + i];
            float p = psm[ty * 4 + i];
            float* op = out + (size_t)t * KDIM + n0 + tx * 4;
            atomicAdd(op + 0, acc[i][0] * p);
            atomicAdd(op + 1, acc[i][1] * p);
            atomicAdd(op + 2, acc[i][2] * p);
            atomicAdd(op + 3, acc[i][3] * p);
        }
    }
}

// ---------------------------------------------------------------------------
// Launcher
// ---------------------------------------------------------------------------
extern "C" void kernel_launch(void* const* d_in, const int* in_sizes, int n_in,
                              void* d_out, int out_size) {
    const float* x    = (const float*)d_in[0];   // hidden_states [T,K]
    const int*   gup  = (const int*)  d_in[1];   // gate_up packed [E,K/8,2I]
    const float* gus  = (const float*)d_in[2];   // gate_up scales [E,K/64,2I]
    const int*   dwp  = (const int*)  d_in[3];   // down packed [E,I/8,K]
    const float* dws  = (const float*)d_in[4];   // down scales [E,I/64,K]
    const int*   sgup = (const int*)  d_in[5];   // shared gate_up packed
    const float* sgus = (const float*)d_in[6];
    const int*   sdp  = (const int*)  d_in[7];   // shared down packed
    const float* sds  = (const float*)d_in[8];
    const int*   ids  = (const int*)  d_in[9];   // expert_ids [T,2]
    const float* probs= (const float*)d_in[10];  // expert_probs [T,2]
    float* out = (float*)d_out;

    // GEMM1 uses 49408 B dynamic smem (> default 48K): raise the cap.
    static const int GEMM1_SMEM = (64 * 64 + 64 * 128 + 64) * 4;
    cudaFuncSetAttribute(k_gemm1, cudaFuncAttributeMaxDynamicSharedMemorySize, GEMM1_SMEM);

    k_zero <<<(T_TOK * KDIM) / 256, 256>>>(out);
    k_route<<<T_TOK / 256, 256>>>(ids, probs);
    k_gemm1<<<dim3(CAP / 64, IDIM / 64, NJOBS), 256, GEMM1_SMEM>>>(x, gup, gus, sgup, sgus);
    k_gemm2<<<dim3(CAP / 64, KDIM / 64, NJOBS), 256>>>(out, dwp, dws, sdp, sds);
}

// round 3
// speedup vs baseline: 5.5904x; 5.5904x over previous
#include <cuda_runtime.h>
#include <cuda_fp16.h>
#include <stdint.h>

#define T_TOK 2048
#define KDIM  2048
#define IDIM  1024
#define NEXP  8
#define NJOBS 9
#define CAP   4096
#define TOPK  2

// ---------------- scratch (device globals) ----------------
__device__ int   g_cnt[NJOBS];
__device__ int   g_tok[NJOBS * CAP];
__device__ float g_prob[NJOBS * CAP];
__device__ __align__(16) __half g_xh[(size_t)T_TOK * KDIM];
__device__ __align__(16) __half g_wgu[(size_t)NJOBS * KDIM * 2 * IDIM];
__device__ __align__(16) __half g_wd [(size_t)NJOBS * IDIM * KDIM];
__device__ __align__(16) __half g_acth[(size_t)NJOBS * CAP * IDIM];

// ---------------- fp4 dequant ----------------
__device__ __forceinline__ float fp4_val(unsigned nib, float half_scale) {
    unsigned mag = (0xC8643210u >> ((nib & 7u) * 4)) & 0xFu;
    float f = (float)mag;
    f = __int_as_float(__float_as_int(f) | ((nib & 8u) << 28));
    return f * half_scale;
}

// ---------------- mma helpers ----------------
__device__ __forceinline__ uint32_t sptr(const void* p) {
    return (uint32_t)__cvta_generic_to_shared(p);
}

__device__ __forceinline__ void ldsm4(uint32_t* r, uint32_t a) {
    asm volatile("ldmatrix.sync.aligned.m8n8.x4.shared.b16 {%0,%1,%2,%3}, [%4];"
        : "=r"(r[0]), "=r"(r[1]), "=r"(r[2]), "=r"(r[3]) : "r"(a));
}

__device__ __forceinline__ void ldsm4t(uint32_t* r, uint32_t a) {
    asm volatile("ldmatrix.sync.aligned.m8n8.x4.trans.shared.b16 {%0,%1,%2,%3}, [%4];"
        : "=r"(r[0]), "=r"(r[1]), "=r"(r[2]), "=r"(r[3]) : "r"(a));
}

__device__ __forceinline__ void mma16816(float* d, const uint32_t* a, uint32_t b0, uint32_t b1) {
    asm volatile("mma.sync.aligned.m16n8k16.row.col.f32.f16.f16.f32 "
        "{%0,%1,%2,%3},{%4,%5,%6,%7},{%8,%9},{%0,%1,%2,%3};"
        : "+f"(d[0]), "+f"(d[1]), "+f"(d[2]), "+f"(d[3])
        : "r"(a[0]), "r"(a[1]), "r"(a[2]), "r"(a[3]), "r"(b0), "r"(b1));
}

// ---------------- kernel 0: zero out + counters ----------------
__global__ void k_zero(float* __restrict__ out) {
    int i = blockIdx.x * 256 + threadIdx.x;
    out[i] = 0.0f;
    if (blockIdx.x == 0 && threadIdx.x < NJOBS) g_cnt[threadIdx.x] = 0;
}

// ---------------- kernel 1: routing ----------------
__global__ void k_route(const int* __restrict__ ids, const float* __restrict__ probs) {
    int t = blockIdx.x * 256 + threadIdx.x;
    for (int s = 0; s < TOPK; s++) {
        int e   = ids[t * TOPK + s];
        float p = probs[t * TOPK + s];
        int pos = atomicAdd(&g_cnt[e], 1);
        g_tok[e * CAP + pos]  = t;
        g_prob[e * CAP + pos] = p;
    }
    g_tok[NEXP * CAP + t]  = t;
    g_prob[NEXP * CAP + t] = 1.0f;
    if (t == 0) g_cnt[NEXP] = T_TOK;
}

// ---------------- kernel 2: x -> fp16 ----------------
__global__ void k_x2h(const float* __restrict__ x) {
    int i = blockIdx.x * 256 + threadIdx.x;
    g_xh[i] = __float2half_rn(x[i]);
}

// ---------------- kernels 3/4: weight dequant -> fp16 ----------------
__global__ void k_dq_gu(const int* __restrict__ wq, const float* __restrict__ sc,
                        const int* __restrict__ wqs, const float* __restrict__ scs) {
    const int job = blockIdx.y;
    const int kw  = blockIdx.x >> 3;
    const int n   = ((blockIdx.x & 7) << 8) + threadIdx.x;
    const int N   = 2 * IDIM;
    const int* W; const float* S;
    if (job < NEXP) { W = wq + (size_t)job * (KDIM / 8) * N; S = sc + (size_t)job * (KDIM / 64) * N; }
    else            { W = wqs; S = scs; }
    unsigned word = (unsigned)W[(size_t)kw * N + n];
    float hs = S[(size_t)(kw >> 3) * N + n] * 0.5f;
    __half* o = g_wgu + (size_t)job * KDIM * N + (size_t)(kw * 8) * N + n;
    for (int j = 0; j < 8; j++) {
        o[(size_t)j * N] = __float2half_rn(fp4_val((word >> (4 * j)) & 0xFu, hs));
    }
}

__global__ void k_dq_dn(const int* __restrict__ wq, const float* __restrict__ sc,
                        const int* __restrict__ wqs, const float* __restrict__ scs) {
    const int job = blockIdx.y;
    const int iw  = blockIdx.x >> 3;
    const int n   = ((blockIdx.x & 7) << 8) + threadIdx.x;
    const int N   = KDIM;
    const int* W; const float* S;
    if (job < NEXP) { W = wq + (size_t)job * (IDIM / 8) * N; S = sc + (size_t)job * (IDIM / 64) * N; }
    else            { W = wqs; S = scs; }
    unsigned word = (unsigned)W[(size_t)iw * N + n];
    float hs = S[(size_t)(iw >> 3) * N + n] * 0.5f;
    __half* o = g_wd + (size_t)job * IDIM * N + (size_t)(iw * 8) * N + n;
    for (int j = 0; j < 8; j++) {
        o[(size_t)j * N] = __float2half_rn(fp4_val((word >> (4 * j)) & 0xFu, hs));
    }
}

// ---------------- kernel 5: gate_up HMMA GEMM + silu ----------------
// 128 threads = 4 warps (2x2). Tile: 64 tok x 64 act-cols, BK=32.
__global__ __launch_bounds__(128) void k_gemm1() {
    __shared__ __align__(16) __half As[64 * 40];
    __shared__ __align__(16) __half Bs[32 * 136];
    __shared__ int ts[64];

    const int job  = blockIdx.z;
    const int cnt  = g_cnt[job];
    const int base = blockIdx.x * 64;
    if (base >= cnt) return;

    const int n0   = blockIdx.y * 64;
    const int tid  = threadIdx.x;
    const int lane = tid & 31;
    const int warp = tid >> 5;
    const int wm   = (warp >> 1) * 32;
    const int wn   = (warp & 1) * 32;
    const __half* Wb = g_wgu + (size_t)job * KDIM * (2 * IDIM);

    if (tid < 64) {
        int p = base + tid;
        ts[tid] = (p < cnt) ? g_tok[job * CAP + p] : -1;
    }
    __syncthreads();

    const int ar0 = tid >> 2;
    const int as0 = (tid & 3) * 8;
    const int t0  = ts[ar0];
    const int t1  = ts[ar0 + 32];
    const __half* ap0 = g_xh + (size_t)(t0 < 0 ? 0 : t0) * KDIM + as0;
    const __half* ap1 = g_xh + (size_t)(t1 < 0 ? 0 : t1) * KDIM + as0;

    int brow[4];
    int bcols[4];
    int bcolg[4];
    for (int i = 0; i < 4; i++) {
        int c = tid + i * 128;
        brow[i]  = c >> 4;
        int col  = (c & 15) * 8;
        bcols[i] = col;
        bcolg[i] = (col < 64) ? (n0 + col) : (IDIM + n0 + col - 64);
    }

    const uint32_t a_addr0 = sptr(&As[(wm + (lane & 7) + ((lane >> 3) & 1) * 8) * 40 + (lane >> 4) * 8]);
    const uint32_t a_addr1 = a_addr0 + 16 * 40 * 2;
    const uint32_t b_base  = sptr(&Bs[(lane & 15) * 136 + wn + (lane >> 4) * 8]);

    float ag[2][4][4];
    float au[2][4][4];
    for (int i = 0; i < 2; i++)
        for (int j = 0; j < 4; j++)
            for (int k = 0; k < 4; k++) { ag[i][j][k] = 0.f; au[i][j][k] = 0.f; }

    for (int kc = 0; kc < KDIM; kc += 32) {
        uint4 av0 = (t0 >= 0) ? *(const uint4*)(ap0 + kc) : make_uint4(0, 0, 0, 0);
        uint4 av1 = (t1 >= 0) ? *(const uint4*)(ap1 + kc) : make_uint4(0, 0, 0, 0);
        uint4 bv[4];
        for (int i = 0; i < 4; i++) {
            bv[i] = *(const uint4*)(Wb + (size_t)(kc + brow[i]) * (2 * IDIM) + bcolg[i]);
        }
        *(uint4*)&As[ar0 * 40 + as0]        = av0;
        *(uint4*)&As[(ar0 + 32) * 40 + as0] = av1;
        for (int i = 0; i < 4; i++) {
            *(uint4*)&Bs[brow[i] * 136 + bcols[i]] = bv[i];
        }
        __syncthreads();

        for (int ks = 0; ks < 2; ks++) {
            uint32_t a0[4];
            uint32_t a1[4];
            ldsm4(a0, a_addr0 + ks * 32);
            ldsm4(a1, a_addr1 + ks * 32);
            for (int bn = 0; bn < 2; bn++) {
                uint32_t bg[4];
                uint32_t bu[4];
                uint32_t boff = b_base + bn * 32 + ks * (16 * 136 * 2);
                ldsm4t(bg, boff);
                ldsm4t(bu, boff + 64 * 2);
                for (int jj = 0; jj < 2; jj++) {
                    mma16816(ag[0][bn * 2 + jj], a0, bg[jj * 2], bg[jj * 2 + 1]);
                    mma16816(ag[1][bn * 2 + jj], a1, bg[jj * 2], bg[jj * 2 + 1]);
                    mma16816(au[0][bn * 2 + jj], a0, bu[jj * 2], bu[jj * 2 + 1]);
                    mma16816(au[1][bn * 2 + jj], a1, bu[jj * 2], bu[jj * 2 + 1]);
                }
            }
        }
        __syncthreads();
    }

    __half* actb = g_acth + (size_t)job * CAP * IDIM;
    for (int am = 0; am < 2; am++) {
        for (int h = 0; h < 2; h++) {
            int r   = wm + am * 16 + (lane >> 2) + h * 8;
            int pos = base + r;
            if (pos >= cnt) continue;
            __half* orow = actb + (size_t)pos * IDIM;
            for (int j = 0; j < 4; j++) {
                int col = n0 + wn + (j >> 1) * 16 + (j & 1) * 8 + (lane & 3) * 2;
                float g0 = ag[am][j][h * 2 + 0];
                float g1 = ag[am][j][h * 2 + 1];
                float u0 = au[am][j][h * 2 + 0];
                float u1 = au[am][j][h * 2 + 1];
                float o0 = g0 / (1.0f + __expf(-g0)) * u0;
                float o1 = g1 / (1.0f + __expf(-g1)) * u1;
                *(__half2*)(orow + col) = __floats2half2_rn(o0, o1);
            }
        }
    }
}

// ---------------- kernel 6: down HMMA GEMM + weighted atomicAdd ----------------
__global__ __launch_bounds__(128) void k_gemm2(float* __restrict__ out) {
    __shared__ __align__(16) __half As2[64 * 40];
    __shared__ __align__(16) __half Bs2[32 * 72];
    __shared__ int   ts2[64];
    __shared__ float ps2[64];

    const int job  = blockIdx.z;
    const int cnt  = g_cnt[job];
    const int base = blockIdx.x * 64;
    if (base >= cnt) return;

    const int n0   = blockIdx.y * 64;
    const int tid  = threadIdx.x;
    const int lane = tid & 31;
    const int warp = tid >> 5;
    const int wm   = (warp >> 1) * 32;
    const int wn   = (warp & 1) * 32;
    const __half* Wb = g_wd + (size_t)job * IDIM * KDIM;
    const __half* Ab = g_acth + (size_t)job * CAP * IDIM;

    if (tid < 64) {
        int p  = base + tid;
        bool v = p < cnt;
        ts2[tid] = v ? g_tok[job * CAP + p] : 0;
        ps2[tid] = v ? g_prob[job * CAP + p] : 0.0f;
    }
    __syncthreads();

    const int ar0 = tid >> 2;
    const int as0 = (tid & 3) * 8;
    const bool v0 = (base + ar0) < cnt;
    const bool v1 = (base + ar0 + 32) < cnt;
    const __half* ap0 = Ab + (size_t)(base + ar0) * IDIM + as0;
    const __half* ap1 = Ab + (size_t)(v1 ? (base + ar0 + 32) : base) * IDIM + as0;

    const int br0 = tid >> 3;
    const int bs0 = (tid & 7) * 8;

    const uint32_t a_addr0 = sptr(&As2[(wm + (lane & 7) + ((lane >> 3) & 1) * 8) * 40 + (lane >> 4) * 8]);
    const uint32_t a_addr1 = a_addr0 + 16 * 40 * 2;
    const uint32_t b_base  = sptr(&Bs2[(lane & 15) * 72 + wn + (lane >> 4) * 8]);

    float acc[2][4][4];
    for (int i = 0; i < 2; i++)
        for (int j = 0; j < 4; j++)
            for (int k = 0; k < 4; k++) acc[i][j][k] = 0.f;

    for (int kc = 0; kc < IDIM; kc += 32) {
        uint4 av0 = v0 ? *(const uint4*)(ap0 + kc) : make_uint4(0, 0, 0, 0);
        uint4 av1 = v1 ? *(const uint4*)(ap1 + kc) : make_uint4(0, 0, 0, 0);
        uint4 bv0 = *(const uint4*)(Wb + (size_t)(kc + br0) * KDIM + n0 + bs0);
        uint4 bv1 = *(const uint4*)(Wb + (size_t)(kc + br0 + 16) * KDIM + n0 + bs0);
        *(uint4*)&As2[ar0 * 40 + as0]        = av0;
        *(uint4*)&As2[(ar0 + 32) * 40 + as0] = av1;
        *(uint4*)&Bs2[br0 * 72 + bs0]        = bv0;
        *(uint4*)&Bs2[(br0 + 16) * 72 + bs0] = bv1;
        __syncthreads();

        for (int ks = 0; ks < 2; ks++) {
            uint32_t a0[4];
            uint32_t a1[4];
            ldsm4(a0, a_addr0 + ks * 32);
            ldsm4(a1, a_addr1 + ks * 32);
            for (int bn = 0; bn < 2; bn++) {
                uint32_t b[4];
                ldsm4t(b, b_base + bn * 32 + ks * (16 * 72 * 2));
                mma16816(acc[0][bn * 2 + 0], a0, b[0], b[1]);
                mma16816(acc[1][bn * 2 + 0], a1, b[0], b[1]);
                mma16816(acc[0][bn * 2 + 1], a0, b[2], b[3]);
                mma16816(acc[1][bn * 2 + 1], a1, b[2], b[3]);
            }
        }
        __syncthreads();
    }

    for (int am = 0; am < 2; am++) {
        for (int h = 0; h < 2; h++) {
            int r   = wm + am * 16 + (lane >> 2) + h * 8;
            int pos = base + r;
            if (pos >= cnt) continue;
            int   t = ts2[r];
            float p = ps2[r];
            float* ob = out + (size_t)t * KDIM;
            for (int j = 0; j < 4; j++) {
                int col = n0 + wn + (j >> 1) * 16 + (j & 1) * 8 + (lane & 3) * 2;
                atomicAdd(ob + col,     acc[am][j][h * 2 + 0] * p);
                atomicAdd(ob + col + 1, acc[am][j][h * 2 + 1] * p);
            }
        }
    }
}

// ---------------- launcher ----------------
extern "C" void kernel_launch(void* const* d_in, const int* in_sizes, int n_in,
                              void* d_out, int out_size) {
    const float* x     = (const float*)d_in[0];
    const int*   gup   = (const int*)  d_in[1];
    const float* gus   = (const float*)d_in[2];
    const int*   dwp   = (const int*)  d_in[3];
    const float* dws   = (const float*)d_in[4];
    const int*   sgup  = (const int*)  d_in[5];
    const float* sgus  = (const float*)d_in[6];
    const int*   sdp   = (const int*)  d_in[7];
    const float* sds   = (const float*)d_in[8];
    const int*   ids   = (const int*)  d_in[9];
    const float* probs = (const float*)d_in[10];
    float* out = (float*)d_out;

    k_zero <<<(T_TOK * KDIM) / 256, 256>>>(out);
    k_route<<<T_TOK / 256, 256>>>(ids, probs);
    k_x2h  <<<(T_TOK * KDIM) / 256, 256>>>(x);
    k_dq_gu<<<dim3((KDIM / 8) * 8, NJOBS), 256>>>(gup, gus, sgup, sgus);
    k_dq_dn<<<dim3((IDIM / 8) * 8, NJOBS), 256>>>(dwp, dws, sdp, sds);
    k_gemm1<<<dim3(CAP / 64, IDIM / 64, NJOBS), 128>>>();
    k_gemm2<<<dim3(CAP / 64, KDIM / 64, NJOBS), 128>>>(out);
}